// round 1
// baseline (speedup 1.0000x reference)
#include <cuda_runtime.h>
#include <cstdint>

#define NN 8192
#define DIN 256
#define DOUT 32
#define NPOOL 128   // pooling partial blocks

// ---------------- scratch (device globals; no allocation allowed) ----------------
__device__ float g_support[NN * DOUT];          // 1 MB
__device__ float g_logits[NN * DOUT];           // 1 MB
__device__ float g_colmax[DOUT];
__device__ float g_colinv[DOUT];
__device__ float g_part[NPOOL * DOUT * DIN];    // 4 MB

// ---------------- packed fp32x2 helpers (Blackwell FFMA2 path) ----------------
__device__ __forceinline__ unsigned long long pack2(float x) {
    unsigned long long r;
    asm("mov.b64 %0, {%1, %1};" : "=l"(r) : "f"(x));
    return r;
}
__device__ __forceinline__ unsigned long long ffma2(unsigned long long a,
                                                    unsigned long long b,
                                                    unsigned long long c) {
    unsigned long long d;
    asm("fma.rn.f32x2 %0, %1, %2, %3;" : "=l"(d) : "l"(a), "l"(b), "l"(c));
    return d;
}
__device__ __forceinline__ float2 unpack2(unsigned long long v) {
    float2 f;
    asm("mov.b64 {%0, %1}, %2;" : "=f"(f.x), "=f"(f.y) : "l"(v));
    return f;
}

// ---------------------------------------------------------------------------
// C[M x 32] = A[M x K] @ S[K x 32]   (fp32, row-major everywhere)
// grid = M/64 CTAs, 256 threads (8 warps). Warps split K 8 ways, chunk = 32 k.
// Per-warp SMEM: a_buf[32][65] (transposed, padded), s_buf[32][32].
// Epilogue: fixed-order 8-way partial reduce through SMEM (deterministic).
// ---------------------------------------------------------------------------
#define ABUF_STRIDE (32 * 65)           // floats per warp
#define SBUF_BASE   (8 * ABUF_STRIDE)   // float offset of s_buf region
#define GEMM_SMEM_BYTES ((SBUF_BASE + 8 * 32 * 32) * 4)   // 99328 B

__global__ void __launch_bounds__(256, 1)
gemm_n32_kernel(const float* __restrict__ A, const float* __restrict__ S,
                float* __restrict__ C, int K)
{
    extern __shared__ float smem[];
    const int t  = threadIdx.x;
    const int w  = t >> 5;
    const int l  = t & 31;
    const int rb = blockIdx.x * 64;

    float* a_buf = smem + w * ABUF_STRIDE;
    float* s_buf = smem + SBUF_BASE + w * (32 * 32);

    const int kslice = K >> 3;        // per-warp K span
    const int nchunk = kslice >> 5;   // chunks of 32
    const int k0 = w * kslice;

    unsigned long long acc0[16], acc1[16];
#pragma unroll
    for (int i = 0; i < 16; i++) { acc0[i] = 0ull; acc1[i] = 0ull; }

    for (int ch = 0; ch < nchunk; ch++) {
        const int kc = k0 + ch * 32;
        __syncwarp();
        // ---- stage A: 64 rows x 32 k -> transposed [k][row], pad 65 ----
        // lane l, iter j: float4 index f = j*32+l ; row = f/8 ; k4 = (f%8)*4
        // LDG: 8 lanes cover one row's 128B (4 lines / instr). STS: conflict-free
        // because (4*(l%8) + i + 4*j + l/8) mod 32 is a permutation over lanes.
#pragma unroll
        for (int j = 0; j < 16; j++) {
            int f   = j * 32 + l;
            int row = f >> 3;
            int k4  = (f & 7) << 2;
            float4 v = *reinterpret_cast<const float4*>(
                A + (size_t)(rb + row) * K + kc + k4);
            a_buf[(k4 + 0) * 65 + row] = v.x;
            a_buf[(k4 + 1) * 65 + row] = v.y;
            a_buf[(k4 + 2) * 65 + row] = v.z;
            a_buf[(k4 + 3) * 65 + row] = v.w;
        }
        // ---- stage S: 32 k x 32 c (contiguous, fully coalesced) ----
#pragma unroll
        for (int j = 0; j < 8; j++) {
            int f = j * 32 + l;
            *reinterpret_cast<float4*>(s_buf + f * 4) =
                *reinterpret_cast<const float4*>(S + (size_t)kc * 32 + f * 4);
        }
        __syncwarp();
        // ---- compute: lane owns rows (l, l+32) x all 32 cols ----
#pragma unroll 4
        for (int k = 0; k < 32; k++) {
            unsigned long long a0 = pack2(a_buf[k * 65 + l]);
            unsigned long long a1 = pack2(a_buf[k * 65 + l + 32]);
            const ulonglong2* s2 =
                reinterpret_cast<const ulonglong2*>(s_buf + k * 32);
#pragma unroll
            for (int c = 0; c < 8; c++) {
                ulonglong2 sv = s2[c];                 // LDS.128 broadcast
                acc0[2 * c]     = ffma2(a0, sv.x, acc0[2 * c]);
                acc0[2 * c + 1] = ffma2(a0, sv.y, acc0[2 * c + 1]);
                acc1[2 * c]     = ffma2(a1, sv.x, acc1[2 * c]);
                acc1[2 * c + 1] = ffma2(a1, sv.y, acc1[2 * c + 1]);
            }
        }
    }

    // ---- cross-warp reduce (fixed order -> deterministic) ----
    __syncthreads();
    float* red = smem;  // overlay: [8][64][33] = 67584 B <= GEMM_SMEM_BYTES
#pragma unroll
    for (int c = 0; c < 16; c++) {
        float2 v0 = unpack2(acc0[c]);
        float2 v1 = unpack2(acc1[c]);
        red[(w * 64 + l) * 33 + 2 * c]          = v0.x;
        red[(w * 64 + l) * 33 + 2 * c + 1]      = v0.y;
        red[(w * 64 + l + 32) * 33 + 2 * c]     = v1.x;
        red[(w * 64 + l + 32) * 33 + 2 * c + 1] = v1.y;
    }
    __syncthreads();
    {
        // thread t reduces 8 contiguous outputs: row = t/4, c0 = (t%4)*8
        int row = t >> 2;
        int c0  = (t & 3) * 8;
        float r[8];
#pragma unroll
        for (int i = 0; i < 8; i++) r[i] = 0.0f;
#pragma unroll
        for (int ww = 0; ww < 8; ww++) {
            const float* p = red + (ww * 64 + row) * 33 + c0;
#pragma unroll
            for (int i = 0; i < 8; i++) r[i] += p[i];
        }
        float4* dst = reinterpret_cast<float4*>(C + (size_t)(rb + row) * 32 + c0);
        dst[0] = make_float4(r[0], r[1], r[2], r[3]);
        dst[1] = make_float4(r[4], r[5], r[6], r[7]);
    }
}

// ---------------------------------------------------------------------------
// Per-column (axis 0) softmax stats: max and 1/sum(exp). b is a per-column
// constant so softmax(x + b) == softmax(x): b is dropped entirely.
// ---------------------------------------------------------------------------
__global__ void softmax_stats_kernel()
{
    const int c = blockIdx.x;
    const int t = threadIdx.x;   // 256
    __shared__ float sred[256];

    float mx = -3.4e38f;
    for (int i = t; i < NN; i += 256)
        mx = fmaxf(mx, g_logits[i * DOUT + c]);
    sred[t] = mx;
    __syncthreads();
    for (int s = 128; s > 0; s >>= 1) {
        if (t < s) sred[t] = fmaxf(sred[t], sred[t + s]);
        __syncthreads();
    }
    mx = sred[0];
    __syncthreads();

    float sum = 0.0f;
    for (int i = t; i < NN; i += 256)
        sum += __expf(g_logits[i * DOUT + c] - mx);
    sred[t] = sum;
    __syncthreads();
    for (int s = 128; s > 0; s >>= 1) {
        if (t < s) sred[t] += sred[t + s];
        __syncthreads();
    }
    if (t == 0) {
        g_colmax[c] = mx;
        g_colinv[c] = 1.0f / sred[0];
    }
}

// ---------------------------------------------------------------------------
// Pooling partials: part[blk][c][d] = sum_{i in blk} softmax(i,c) * X[i][d]
// grid = 128 CTAs x 64 rows, 256 threads (thread t = feature d).
// ---------------------------------------------------------------------------
__global__ void __launch_bounds__(256, 1)
pool_kernel(const float* __restrict__ X)
{
    __shared__ float wsm[64 * DOUT];
    const int t  = threadIdx.x;
    const int rb = blockIdx.x * 64;

#pragma unroll
    for (int q = 0; q < 8; q++) {
        int idx = t * 8 + q;                 // 0..2047
        int il  = idx >> 5;
        int c   = idx & 31;
        float lg = g_logits[(size_t)(rb + il) * DOUT + c];
        wsm[idx] = __expf(lg - g_colmax[c]) * g_colinv[c];
    }
    __syncthreads();

    unsigned long long acc[16];
#pragma unroll
    for (int i = 0; i < 16; i++) acc[i] = 0ull;

    for (int il = 0; il < 64; il++) {
        float x = X[(size_t)(rb + il) * DIN + t];     // coalesced
        unsigned long long xp = pack2(x);
        const ulonglong2* wv =
            reinterpret_cast<const ulonglong2*>(wsm + il * DOUT);
#pragma unroll
        for (int c = 0; c < 8; c++) {
            ulonglong2 sv = wv[c];                    // LDS.128 broadcast
            acc[2 * c]     = ffma2(xp, sv.x, acc[2 * c]);
            acc[2 * c + 1] = ffma2(xp, sv.y, acc[2 * c + 1]);
        }
    }

    float* pp = g_part + (size_t)blockIdx.x * (DOUT * DIN);
#pragma unroll
    for (int c = 0; c < 16; c++) {
        float2 v = unpack2(acc[c]);
        pp[(2 * c) * DIN + t]     = v.x;
        pp[(2 * c + 1) * DIN + t] = v.y;
    }
}

// ---------------------------------------------------------------------------
// Final fixed-order reduce over the 128 pooling partials -> out[32][256]
// ---------------------------------------------------------------------------
__global__ void reduce_out_kernel(float* __restrict__ out)
{
    const int c = blockIdx.x;     // 32
    const int t = threadIdx.x;    // 256
    float s = 0.0f;
    for (int b = 0; b < NPOOL; b++)
        s += g_part[(size_t)b * (DOUT * DIN) + c * DIN + t];
    out[c * DIN + t] = s;
}

// ---------------------------------------------------------------------------
extern "C" void kernel_launch(void* const* d_in, const int* in_sizes, int n_in,
                              void* d_out, int out_size)
{
    const float* X = (const float*)d_in[0];   // main_feat [8192,256]
    const float* A = (const float*)d_in[1];   // main_adj  [8192,8192]
    const float* W = (const float*)d_in[2];   // W         [256,32]
    // d_in[3] = b: per-column constant, softmax over axis 0 is invariant -> dropped
    float* out = (float*)d_out;

    float *sup, *logits;
    cudaGetSymbolAddress((void**)&sup, g_support);
    cudaGetSymbolAddress((void**)&logits, g_logits);

    cudaFuncSetAttribute(gemm_n32_kernel,
                         cudaFuncAttributeMaxDynamicSharedMemorySize,
                         GEMM_SMEM_BYTES);

    // 1) support = X @ W
    gemm_n32_kernel<<<NN / 64, 256, GEMM_SMEM_BYTES>>>(X, W, sup, DIN);
    // 2) logits = A @ support   (b dropped; softmax-invariant)
    gemm_n32_kernel<<<NN / 64, 256, GEMM_SMEM_BYTES>>>(A, sup, logits, NN);
    // 3) per-column softmax stats
    softmax_stats_kernel<<<DOUT, 256>>>();
    // 4) weighted pooling partials
    pool_kernel<<<NPOOL, 256>>>(X);
    // 5) deterministic final reduce
    reduce_out_kernel<<<DOUT, 256>>>(out);
}